// round 2
// baseline (speedup 1.0000x reference)
#include <cuda_runtime.h>
#include <math.h>

#define H 1024
#define W 1024
#define NPIX (H * W)
#define NSL 16                 // 8 pred slices + 8 target slices
#define HALF (8 * NPIX)        // elements per image set

#define TX 64
#define TY 16

// Persistent scratch (allocation-free rule: __device__ globals)
__device__ float g_img0[NSL * NPIX];   // [0:HALF) = sigmoid(pred), [HALF:) = float(target)
__device__ float g_bufA[NSL * NPIX];
__device__ float g_bufB[NSL * NPIX];
__device__ float g_skel[NSL * NPIX];
__device__ float g_acc[8];             // 7 sums used

__global__ void zero_acc_kernel() {
    if (threadIdx.x < 8) g_acc[threadIdx.x] = 0.0f;
}

__global__ void init_kernel(const float* __restrict__ pred,
                            const int* __restrict__ target) {
    int i = blockIdx.x * blockDim.x + threadIdx.x;
    if (i < HALF) {
        float x = pred[i];
        g_img0[i] = 1.0f / (1.0f + __expf(-x));
        g_img0[HALF + i] = (float)target[i];
    }
}

// One skeleton step: reads e_k, computes e_{k+1} = erode(e_k) (cross-min),
// delta_k = relu(e_k - dilate3x3(e_{k+1})), updates skel, writes e_{k+1}.
// src_sel/dst_sel choose among the device-global buffers (avoids symbol addr).
__global__ __launch_bounds__(TX * TY)
void step_kernel(int src_sel, int dst_sel, int kstep) {
    __shared__ float s0[TY + 4][TX + 4];      // e_k tile with halo 2 (+inf padded)
    __shared__ float s1[TY + 2][TX + 2 + 1];  // erode(e_k) with halo 1 (-inf at OOB)

    const float* in = (src_sel == 0) ? g_img0 : ((src_sel == 1) ? g_bufA : g_bufB);
    float* out = (dst_sel == 1) ? g_bufA : g_bufB;

    const int bx = blockIdx.x * TX;
    const int by = blockIdx.y * TY;
    const int z  = blockIdx.z;
    const float* img = in + (size_t)z * NPIX;

    const int tid = threadIdx.y * TX + threadIdx.x;
    const int NT = TX * TY;

    // Stage 0: load e_k tile with halo 2, +inf outside image
    for (int i = tid; i < (TY + 4) * (TX + 4); i += NT) {
        int ly = i / (TX + 4), lx = i % (TX + 4);
        int gx = bx - 2 + lx, gy = by - 2 + ly;
        float v = INFINITY;
        if (gx >= 0 && gx < W && gy >= 0 && gy < H) v = img[gy * W + gx];
        s0[ly][lx] = v;
    }
    __syncthreads();

    // Stage 1: erode (5-point cross min) at halo-1 positions.
    // Out-of-image positions get -inf so the dilate max ignores them.
    for (int i = tid; i < (TY + 2) * (TX + 2); i += NT) {
        int ly = i / (TX + 2), lx = i % (TX + 2);
        int gx = bx - 1 + lx, gy = by - 1 + ly;
        float v;
        if (gx >= 0 && gx < W && gy >= 0 && gy < H) {
            float c = s0[ly + 1][lx + 1];
            float vmin = fminf(fminf(s0[ly][lx + 1], s0[ly + 2][lx + 1]),
                               fminf(s0[ly + 1][lx], s0[ly + 1][lx + 2]));
            v = fminf(c, vmin);
        } else {
            v = -INFINITY;
        }
        s1[ly][lx] = v;
    }
    __syncthreads();

    const int tx = threadIdx.x, ty = threadIdx.y;
    const int gx = bx + tx, gy = by + ty;
    const size_t gi = (size_t)z * NPIX + (size_t)gy * W + gx;

    float e1 = s1[ty + 1][tx + 1];
    if (kstep < 10) out[gi] = e1;   // e_11 never consumed -> skip final write

    // dilate3x3 of e_{k+1}
    float d = e1;
    #pragma unroll
    for (int dy = 0; dy < 3; dy++) {
        #pragma unroll
        for (int dx = 0; dx < 3; dx++) {
            d = fmaxf(d, s1[ty + dy][tx + dx]);
        }
    }

    float ek = s0[ty + 2][tx + 2];
    float delta = fmaxf(ek - d, 0.0f);

    if (kstep == 0) {
        g_skel[gi] = delta;
    } else {
        float sk = g_skel[gi];
        g_skel[gi] = sk + fmaxf(delta - sk * delta, 0.0f);
    }
}

__global__ void reduce_kernel() {
    float a0 = 0.f, a1 = 0.f, a2 = 0.f, a3 = 0.f, a4 = 0.f, a5 = 0.f, a6 = 0.f;
    for (int i = blockIdx.x * blockDim.x + threadIdx.x; i < HALF;
         i += gridDim.x * blockDim.x) {
        float p  = g_img0[i];
        float t  = g_img0[HALF + i];
        float sp = g_skel[i];
        float st = g_skel[HALF + i];
        a0 += sp * t;   // sum(skel_pred * target)
        a1 += sp;       // sum(skel_pred)
        a2 += st * p;   // sum(skel_target * pred_prob)
        a3 += st;       // sum(skel_target)
        a4 += p * t;    // sum(p*t)
        a5 += p;        // sum(p)
        a6 += t;        // sum(t)
    }
    #pragma unroll
    for (int o = 16; o > 0; o >>= 1) {
        a0 += __shfl_down_sync(0xffffffffu, a0, o);
        a1 += __shfl_down_sync(0xffffffffu, a1, o);
        a2 += __shfl_down_sync(0xffffffffu, a2, o);
        a3 += __shfl_down_sync(0xffffffffu, a3, o);
        a4 += __shfl_down_sync(0xffffffffu, a4, o);
        a5 += __shfl_down_sync(0xffffffffu, a5, o);
        a6 += __shfl_down_sync(0xffffffffu, a6, o);
    }
    if ((threadIdx.x & 31) == 0) {
        atomicAdd(&g_acc[0], a0);
        atomicAdd(&g_acc[1], a1);
        atomicAdd(&g_acc[2], a2);
        atomicAdd(&g_acc[3], a3);
        atomicAdd(&g_acc[4], a4);
        atomicAdd(&g_acc[5], a5);
        atomicAdd(&g_acc[6], a6);
    }
}

__global__ void finalize_kernel(float* out) {
    const float SMOOTH = 1.0f;
    float tprec = (g_acc[0] + SMOOTH) / (g_acc[1] + SMOOTH);
    float tsens = (g_acc[2] + SMOOTH) / (g_acc[3] + SMOOTH);
    float cl_dice = 2.0f * tprec * tsens / (tprec + tsens + 1e-7f);
    float dice = (2.0f * g_acc[4] + SMOOTH) / (g_acc[5] + g_acc[6] + SMOOTH);
    float combined = 0.5f * dice + 0.5f * cl_dice;
    out[0] = 1.0f - combined;
}

extern "C" void kernel_launch(void* const* d_in, const int* in_sizes, int n_in,
                              void* d_out, int out_size) {
    const float* pred  = (const float*)d_in[0];
    const int* target  = (const int*)d_in[1];

    zero_acc_kernel<<<1, 32>>>();
    init_kernel<<<(HALF + 255) / 256, 256>>>(pred, target);

    dim3 blk(TX, TY);
    dim3 grd(W / TX, H / TY, NSL);
    int src = 0;
    for (int k = 0; k < 11; k++) {
        int dst = (k % 2 == 0) ? 1 : 2;
        step_kernel<<<grd, blk>>>(src, dst, k);
        src = dst;
    }

    reduce_kernel<<<2048, 256>>>();
    finalize_kernel<<<1, 1>>>((float*)d_out);
}

// round 4
// speedup vs baseline: 3.0215x; 3.0215x over previous
#include <cuda_runtime.h>
#include <math.h>

#define H 1024
#define W 1024
#define NPIX (H * W)
#define NSL 16                 // 8 pred slices + 8 target slices
#define HALF (8 * NPIX)

#define TXO 128
#define TYO 16

// Persistent scratch (allocation-free rule: __device__ globals)
__device__ float g_img0[NSL * NPIX];
__device__ float g_bufA[NSL * NPIX];
__device__ float g_bufB[NSL * NPIX];
__device__ float g_skel[NSL * NPIX];
__device__ float g_acc[8];

__global__ void zero_acc_kernel() {
    if (threadIdx.x < 8) g_acc[threadIdx.x] = 0.0f;
}

// sigmoid(pred) + float(target) -> g_img0, and accumulate dice sums (p*t, p, t)
__global__ void init_kernel(const float* __restrict__ pred,
                            const int* __restrict__ tgt) {
    float a4 = 0.f, a5 = 0.f, a6 = 0.f;
    const int stride = gridDim.x * blockDim.x;
    for (int i = blockIdx.x * blockDim.x + threadIdx.x; i < HALF; i += stride) {
        float p = 1.0f / (1.0f + __expf(-pred[i]));
        float t = (float)tgt[i];
        g_img0[i] = p;
        g_img0[HALF + i] = t;
        a4 += p * t; a5 += p; a6 += t;
    }
    #pragma unroll
    for (int o = 16; o; o >>= 1) {
        a4 += __shfl_down_sync(0xffffffffu, a4, o);
        a5 += __shfl_down_sync(0xffffffffu, a5, o);
        a6 += __shfl_down_sync(0xffffffffu, a6, o);
    }
    __shared__ float sr[3][8];
    int w = threadIdx.x >> 5, l = threadIdx.x & 31;
    if (l == 0) { sr[0][w] = a4; sr[1][w] = a5; sr[2][w] = a6; }
    __syncthreads();
    if (threadIdx.x == 0) {
        float s4 = 0.f, s5 = 0.f, s6 = 0.f;
        #pragma unroll
        for (int k = 0; k < 8; k++) { s4 += sr[0][k]; s5 += sr[1][k]; s6 += sr[2][k]; }
        atomicAdd(&g_acc[4], s4);
        atomicAdd(&g_acc[5], s5);
        atomicAdd(&g_acc[6], s6);
    }
}

// Fused F skeleton steps entirely in shared memory.
// Each step: e' = erode(e) (5-pt cross min, +inf pad), delta = relu(e - dilate3x3(e')),
// skel += relu(delta - skel*delta) (registers). Ping-pong smem stages.
template<int F, bool FIRST, bool LAST>
__global__ __launch_bounds__(1024)
void fused_kernel(int src_sel, int dst_sel) {
    constexpr int R  = F + 1;
    constexpr int W2 = TXO + 2 * R;
    constexpr int H2 = TYO + 2 * R;

    __shared__ float sA[H2 * W2];
    __shared__ float sB[H2 * W2];
    __shared__ float sred[64];

    const float* in = (src_sel == 0) ? g_img0 : ((src_sel == 1) ? g_bufA : g_bufB);
    float* eout = (dst_sel == 1) ? g_bufA : g_bufB;

    const int bx = blockIdx.x * TXO;
    const int by = blockIdx.y * TYO;
    const int z  = blockIdx.z;
    const float* img = in + (size_t)z * NPIX;
    const int tid = threadIdx.y * 128 + threadIdx.x;
    const bool border = (blockIdx.x == 0) | (blockIdx.x == gridDim.x - 1) |
                        (blockIdx.y == 0) | (blockIdx.y == gridDim.y - 1);

    // Load e_k tile with halo R (+inf outside image)
    if (!border) {
        for (int i = tid; i < H2 * W2; i += 1024) {
            int ly = i / W2, lx = i - ly * W2;
            sA[i] = img[(by - R + ly) * W + (bx - R + lx)];
        }
    } else {
        for (int i = tid; i < H2 * W2; i += 1024) {
            int ly = i / W2, lx = i - ly * W2;
            int gxx = bx - R + lx, gyy = by - R + ly;
            float v = INFINITY;
            if ((unsigned)gxx < W && (unsigned)gyy < H) v = img[gyy * W + gxx];
            sA[i] = v;
        }
    }

    const int tx  = threadIdx.x;          // 0..127
    const int ty0 = threadIdx.y;          // 0..7
    const int ty1 = threadIdx.y + 8;
    const int gx  = bx + tx;
    const size_t gi0 = (size_t)z * NPIX + (size_t)(by + ty0) * W + gx;
    const size_t gi1 = (size_t)z * NPIX + (size_t)(by + ty1) * W + gx;

    float sk0, sk1;
    if (FIRST) { sk0 = 0.f; sk1 = 0.f; }
    else       { sk0 = g_skel[gi0]; sk1 = g_skel[gi1]; }
    __syncthreads();

    float* S  = sA;
    float* S2 = sB;

    #pragma unroll
    for (int st = 0; st < F; st++) {
        // erode over all interior positions (rings >= 1); shrinking validity
        // means outer-ring results beyond ring st+1 are garbage but unconsumed.
        for (int i = tid; i < (H2 - 2) * (W2 - 2); i += 1024) {
            int ly = i / (W2 - 2);
            int lx = i - ly * (W2 - 2) + 1;
            ly += 1;
            int o = ly * W2 + lx;
            float v = fminf(S[o],
                      fminf(fminf(S[o - W2], S[o + W2]),
                            fminf(S[o - 1],  S[o + 1])));
            if (border) {
                int gxx = bx - R + lx, gyy = by - R + ly;
                if (!((unsigned)gxx < W && (unsigned)gyy < H)) v = INFINITY;
            }
            S2[o] = v;
        }
        __syncthreads();

        // dilate3x3(e') + delta + skel update at this thread's 2 output pixels
        auto do_pixel = [&](int py, int gy, float& sk) {
            int c0 = (R + py) * W2 + (R + tx);
            float c = S[c0];       // e_k at center (S intact; S2 is separate)
            float d;
            if (!border) {
                d =              S2[c0 - W2 - 1];
                d = fmaxf(d,     S2[c0 - W2]);
                d = fmaxf(d,     S2[c0 - W2 + 1]);
                d = fmaxf(d,     S2[c0 - 1]);
                d = fmaxf(d,     S2[c0]);
                d = fmaxf(d,     S2[c0 + 1]);
                d = fmaxf(d,     S2[c0 + W2 - 1]);
                d = fmaxf(d,     S2[c0 + W2]);
                d = fmaxf(d,     S2[c0 + W2 + 1]);
            } else {
                d = -INFINITY;
                #pragma unroll
                for (int dy = -1; dy <= 1; dy++) {
                    #pragma unroll
                    for (int dx = -1; dx <= 1; dx++) {
                        int gxx = gx + dx, gyy = gy + dy;
                        if ((unsigned)gxx < W && (unsigned)gyy < H)
                            d = fmaxf(d, S2[c0 + dy * W2 + dx]);
                    }
                }
            }
            float delta = fmaxf(c - d, 0.0f);
            if (FIRST && st == 0) sk = delta;
            else                  sk = sk + fmaxf(delta - sk * delta, 0.0f);
        };
        do_pixel(ty0, by + ty0, sk0);
        do_pixel(ty1, by + ty1, sk1);
        __syncthreads();   // before next erode overwrites old S

        float* tmp = S; S = S2; S2 = tmp;
    }

    const int c00 = (R + ty0) * W2 + (R + tx);
    const int c01 = (R + ty1) * W2 + (R + tx);

    if (!LAST) {
        eout[gi0] = S[c00];
        eout[gi1] = S[c01];
        g_skel[gi0] = sk0;
        g_skel[gi1] = sk1;
    } else {
        // accumulate skeleton sums: pred slices need target value, and vice versa
        float cp0 = (z < 8) ? g_img0[gi0 + HALF] : g_img0[gi0 - HALF];
        float cp1 = (z < 8) ? g_img0[gi1 + HALF] : g_img0[gi1 - HALF];
        float sprod = sk0 * cp0 + sk1 * cp1;
        float ssum  = sk0 + sk1;
        #pragma unroll
        for (int o = 16; o; o >>= 1) {
            sprod += __shfl_down_sync(0xffffffffu, sprod, o);
            ssum  += __shfl_down_sync(0xffffffffu, ssum,  o);
        }
        int w = tid >> 5, l = tid & 31;
        if (l == 0) { sred[w] = sprod; sred[32 + w] = ssum; }
        __syncthreads();
        if (tid < 32) {
            float a = sred[tid], b = sred[32 + tid];
            #pragma unroll
            for (int o = 16; o; o >>= 1) {
                a += __shfl_down_sync(0xffffffffu, a, o);
                b += __shfl_down_sync(0xffffffffu, b, o);
            }
            if (tid == 0) {
                if (z < 8) { atomicAdd(&g_acc[0], a); atomicAdd(&g_acc[1], b); }
                else       { atomicAdd(&g_acc[2], a); atomicAdd(&g_acc[3], b); }
            }
        }
    }
}

__global__ void finalize_kernel(float* out) {
    const float SMOOTH = 1.0f;
    float tprec = (g_acc[0] + SMOOTH) / (g_acc[1] + SMOOTH);
    float tsens = (g_acc[2] + SMOOTH) / (g_acc[3] + SMOOTH);
    float cl_dice = 2.0f * tprec * tsens / (tprec + tsens + 1e-7f);
    float dice = (2.0f * g_acc[4] + SMOOTH) / (g_acc[5] + g_acc[6] + SMOOTH);
    float combined = 0.5f * dice + 0.5f * cl_dice;
    out[0] = 1.0f - combined;
}

extern "C" void kernel_launch(void* const* d_in, const int* in_sizes, int n_in,
                              void* d_out, int out_size) {
    const float* pred = (const float*)d_in[0];
    const int* target = (const int*)d_in[1];

    zero_acc_kernel<<<1, 32>>>();
    init_kernel<<<2048, 256>>>(pred, target);

    dim3 blk(128, 8);
    dim3 grd(W / TXO, H / TYO, NSL);
    // steps 0-3
    fused_kernel<4, true,  false><<<grd, blk>>>(0, 1);
    // steps 4-7
    fused_kernel<4, false, false><<<grd, blk>>>(1, 2);
    // steps 8-10 (no e-output; folds in the skeleton reductions)
    fused_kernel<3, false, true ><<<grd, blk>>>(2, 1);

    finalize_kernel<<<1, 1>>>((float*)d_out);
}

// round 5
// speedup vs baseline: 3.2514x; 1.0761x over previous
#include <cuda_runtime.h>
#include <math.h>

#define H 1024
#define W 1024
#define NPIX (H * W)
#define NSL 16
#define HALF (8 * NPIX)

#define TXO 128
#define TYO 32
#define PADX 8
#define W2 144          // padded smem row (floats); center pixels at lx = 8..135

__device__ float g_img0[NSL * NPIX];
__device__ float g_bufA[NSL * NPIX];
__device__ float g_bufB[NSL * NPIX];
__device__ float g_skel[NSL * NPIX];
__device__ float g_acc[8];

__global__ void zero_acc_kernel() {
    if (threadIdx.x < 8) g_acc[threadIdx.x] = 0.0f;
}

__global__ void init_kernel(const float4* __restrict__ pred,
                            const int4* __restrict__ tgt) {
    float a4 = 0.f, a5 = 0.f, a6 = 0.f;
    const int n4 = HALF / 4;
    float4* img4 = (float4*)g_img0;
    const int stride = gridDim.x * blockDim.x;
    for (int i = blockIdx.x * blockDim.x + threadIdx.x; i < n4; i += stride) {
        float4 x = pred[i];
        int4 ti = tgt[i];
        float4 p, t;
        p.x = 1.0f / (1.0f + __expf(-x.x));
        p.y = 1.0f / (1.0f + __expf(-x.y));
        p.z = 1.0f / (1.0f + __expf(-x.z));
        p.w = 1.0f / (1.0f + __expf(-x.w));
        t.x = (float)ti.x; t.y = (float)ti.y; t.z = (float)ti.z; t.w = (float)ti.w;
        img4[i] = p;
        img4[n4 + i] = t;
        a4 += p.x * t.x + p.y * t.y + p.z * t.z + p.w * t.w;
        a5 += p.x + p.y + p.z + p.w;
        a6 += t.x + t.y + t.z + t.w;
    }
    #pragma unroll
    for (int o = 16; o; o >>= 1) {
        a4 += __shfl_down_sync(0xffffffffu, a4, o);
        a5 += __shfl_down_sync(0xffffffffu, a5, o);
        a6 += __shfl_down_sync(0xffffffffu, a6, o);
    }
    __shared__ float sr[3][8];
    int w = threadIdx.x >> 5, l = threadIdx.x & 31;
    if (l == 0) { sr[0][w] = a4; sr[1][w] = a5; sr[2][w] = a6; }
    __syncthreads();
    if (threadIdx.x == 0) {
        float s4 = 0.f, s5 = 0.f, s6 = 0.f;
        #pragma unroll
        for (int k = 0; k < 8; k++) { s4 += sr[0][k]; s5 += sr[1][k]; s6 += sr[2][k]; }
        atomicAdd(&g_acc[4], s4);
        atomicAdd(&g_acc[5], s5);
        atomicAdd(&g_acc[6], s6);
    }
}

template<int F, bool FIRST, bool LAST>
__global__ __launch_bounds__(1024)
void fused_kernel(int src_sel, int dst_sel) {
    constexpr int R  = F + 1;
    constexpr int H2 = TYO + 2 * R;

    __shared__ float sA[H2 * W2];
    __shared__ float sB[H2 * W2];
    __shared__ float sred[64];

    const float* in = (src_sel == 0) ? g_img0 : ((src_sel == 1) ? g_bufA : g_bufB);
    float* eout = (dst_sel == 1) ? g_bufA : g_bufB;

    const int bx = blockIdx.x * TXO;
    const int by = blockIdx.y * TYO;
    const int z  = blockIdx.z;
    const float* img = in + (size_t)z * NPIX;
    const int tx = threadIdx.x;        // 0..31 (x vector)
    const int ty = threadIdx.y;        // 0..31 (row)
    const int tid = ty * 32 + tx;
    const bool border = (blockIdx.x == 0) | (blockIdx.x == gridDim.x - 1) |
                        (blockIdx.y == 0) | (blockIdx.y == gridDim.y - 1);

    // ---- load tile (vectors; OOB whole-vector since boundaries 4-aligned) ----
    if (!border) {
        for (int i = tid; i < 36 * H2; i += 1024) {
            int vy = i / 36, vx = i - vy * 36;
            *(float4*)&sA[vy * W2 + 4 * vx] =
                *(const float4*)&img[(by - R + vy) * W + (bx - PADX + 4 * vx)];
        }
    } else {
        for (int i = tid; i < 36 * H2; i += 1024) {
            int vy = i / 36, vx = i - vy * 36;
            int gx0 = bx - PADX + 4 * vx;
            int gy  = by - R + vy;
            float4 v = make_float4(INFINITY, INFINITY, INFINITY, INFINITY);
            if ((unsigned)gx0 < W && (unsigned)gy < H)
                v = *(const float4*)&img[gy * W + gx0];
            *(float4*)&sA[vy * W2 + 4 * vx] = v;
        }
    }

    const size_t gi = (size_t)z * NPIX + (size_t)(by + ty) * W + (bx + 4 * tx);
    float4 sk;
    if (FIRST) sk = make_float4(0.f, 0.f, 0.f, 0.f);
    else       sk = *(const float4*)&g_skel[gi];
    __syncthreads();

    float* S  = sA;
    float* S2 = sB;

    #pragma unroll
    for (int st = 0; st < F; st++) {
        // ---- erode (5-pt cross min); region x-vecs [1,35), rows [1,H2-1) ----
        constexpr int NE = 34 * (H2 - 2);
        for (int i = tid; i < NE; i += 1024) {
            int ly = i / 34;
            int vx = i - ly * 34 + 1;
            ly += 1;
            int o = ly * W2 + 4 * vx;
            float4 c = *(float4*)&S[o];
            float4 u = *(float4*)&S[o - W2];
            float4 d = *(float4*)&S[o + W2];
            float l = S[o - 1], r = S[o + 4];
            float4 e;
            e.x = fminf(fminf(c.x, fminf(u.x, d.x)), fminf(l,   c.y));
            e.y = fminf(fminf(c.y, fminf(u.y, d.y)), fminf(c.x, c.z));
            e.z = fminf(fminf(c.z, fminf(u.z, d.z)), fminf(c.y, c.w));
            e.w = fminf(fminf(c.w, fminf(u.w, d.w)), fminf(c.z, r));
            if (border) {
                int gx0 = bx - PADX + 4 * vx;
                int gy  = by - R + ly;
                if (!((unsigned)gx0 < W && (unsigned)gy < H)) {
                    e.x = INFINITY; e.y = INFINITY; e.z = INFINITY; e.w = INFINITY;
                }
            }
            *(float4*)&S2[o] = e;
        }
        __syncthreads();

        // ---- dilate3x3(e') + delta + skel at this thread's 4 pixels ----
        {
            int o = (R + ty) * W2 + PADX + 4 * tx;
            float4 vu = *(float4*)&S2[o - W2];
            float4 vm = *(float4*)&S2[o];
            float4 vd = *(float4*)&S2[o + W2];
            float lu = S2[o - W2 - 1], ru = S2[o - W2 + 4];
            float lm = S2[o - 1],      rm = S2[o + 4];
            float ld = S2[o + W2 - 1], rd = S2[o + W2 + 4];
            if (border) {
                const int gy = by + ty;
                const int gx0 = bx + 4 * tx;
                if (gy == 0) {
                    vu = make_float4(-INFINITY, -INFINITY, -INFINITY, -INFINITY);
                    lu = -INFINITY; ru = -INFINITY;
                }
                if (gy == H - 1) {
                    vd = make_float4(-INFINITY, -INFINITY, -INFINITY, -INFINITY);
                    ld = -INFINITY; rd = -INFINITY;
                }
                if (gx0 == 0)     { lu = -INFINITY; lm = -INFINITY; ld = -INFINITY; }
                if (gx0 == W - 4) { ru = -INFINITY; rm = -INFINITY; rd = -INFINITY; }
            }
            float4 hu, hm, hd, dd;
            hu.x = fmaxf(lu,   fmaxf(vu.x, vu.y));
            hu.y = fmaxf(vu.x, fmaxf(vu.y, vu.z));
            hu.z = fmaxf(vu.y, fmaxf(vu.z, vu.w));
            hu.w = fmaxf(vu.z, fmaxf(vu.w, ru));
            hm.x = fmaxf(lm,   fmaxf(vm.x, vm.y));
            hm.y = fmaxf(vm.x, fmaxf(vm.y, vm.z));
            hm.z = fmaxf(vm.y, fmaxf(vm.z, vm.w));
            hm.w = fmaxf(vm.z, fmaxf(vm.w, rm));
            hd.x = fmaxf(ld,   fmaxf(vd.x, vd.y));
            hd.y = fmaxf(vd.x, fmaxf(vd.y, vd.z));
            hd.z = fmaxf(vd.y, fmaxf(vd.z, vd.w));
            hd.w = fmaxf(vd.z, fmaxf(vd.w, rd));
            dd.x = fmaxf(hu.x, fmaxf(hm.x, hd.x));
            dd.y = fmaxf(hu.y, fmaxf(hm.y, hd.y));
            dd.z = fmaxf(hu.z, fmaxf(hm.z, hd.z));
            dd.w = fmaxf(hu.w, fmaxf(hm.w, hd.w));

            float4 ek = *(float4*)&S[o];
            float4 de;
            de.x = fmaxf(ek.x - dd.x, 0.f);
            de.y = fmaxf(ek.y - dd.y, 0.f);
            de.z = fmaxf(ek.z - dd.z, 0.f);
            de.w = fmaxf(ek.w - dd.w, 0.f);
            if (FIRST && st == 0) {
                sk = de;
            } else {
                sk.x += fmaxf(de.x - sk.x * de.x, 0.f);
                sk.y += fmaxf(de.y - sk.y * de.y, 0.f);
                sk.z += fmaxf(de.z - sk.z * de.z, 0.f);
                sk.w += fmaxf(de.w - sk.w * de.w, 0.f);
            }
            if (st == F - 1 && !LAST) {
                *(float4*)&eout[gi] = vm;       // e' center = dilate middle row vec
                *(float4*)&g_skel[gi] = sk;
            }
        }
        __syncthreads();
        float* tmp = S; S = S2; S2 = tmp;
    }

    if (LAST) {
        float4 cp = (z < 8) ? *(const float4*)&g_img0[gi + HALF]
                            : *(const float4*)&g_img0[gi - HALF];
        float sprod = sk.x * cp.x + sk.y * cp.y + sk.z * cp.z + sk.w * cp.w;
        float ssum  = sk.x + sk.y + sk.z + sk.w;
        #pragma unroll
        for (int o = 16; o; o >>= 1) {
            sprod += __shfl_down_sync(0xffffffffu, sprod, o);
            ssum  += __shfl_down_sync(0xffffffffu, ssum,  o);
        }
        int w = tid >> 5, l = tid & 31;
        if (l == 0) { sred[w] = sprod; sred[32 + w] = ssum; }
        __syncthreads();
        if (tid < 32) {
            float a = sred[tid], b = sred[32 + tid];
            #pragma unroll
            for (int o = 16; o; o >>= 1) {
                a += __shfl_down_sync(0xffffffffu, a, o);
                b += __shfl_down_sync(0xffffffffu, b, o);
            }
            if (tid == 0) {
                if (z < 8) { atomicAdd(&g_acc[0], a); atomicAdd(&g_acc[1], b); }
                else       { atomicAdd(&g_acc[2], a); atomicAdd(&g_acc[3], b); }
            }
        }
    }
}

__global__ void finalize_kernel(float* out) {
    const float SMOOTH = 1.0f;
    float tprec = (g_acc[0] + SMOOTH) / (g_acc[1] + SMOOTH);
    float tsens = (g_acc[2] + SMOOTH) / (g_acc[3] + SMOOTH);
    float cl_dice = 2.0f * tprec * tsens / (tprec + tsens + 1e-7f);
    float dice = (2.0f * g_acc[4] + SMOOTH) / (g_acc[5] + g_acc[6] + SMOOTH);
    float combined = 0.5f * dice + 0.5f * cl_dice;
    out[0] = 1.0f - combined;
}

extern "C" void kernel_launch(void* const* d_in, const int* in_sizes, int n_in,
                              void* d_out, int out_size) {
    const float4* pred = (const float4*)d_in[0];
    const int4* target = (const int4*)d_in[1];

    zero_acc_kernel<<<1, 32>>>();
    init_kernel<<<2048, 256>>>(pred, target);

    dim3 blk(32, 32);
    dim3 grd(W / TXO, H / TYO, NSL);
    fused_kernel<4, true,  false><<<grd, blk>>>(0, 1);   // steps 0-3
    fused_kernel<4, false, false><<<grd, blk>>>(1, 2);   // steps 4-7
    fused_kernel<3, false, true ><<<grd, blk>>>(2, 1);   // steps 8-10 + reductions

    finalize_kernel<<<1, 1>>>((float*)d_out);
}

// round 6
// speedup vs baseline: 4.4626x; 1.3725x over previous
#include <cuda_runtime.h>
#include <math.h>

#define H 1024
#define W 1024
#define NPIX (H * W)
#define NSL 16
#define HALF (8 * NPIX)

#define TXO 128
#define TYO 16
#define PADX 8
#define W2 144          // padded smem row; center pixels at lx = 8..135

__device__ float g_img0[NSL * NPIX];
__device__ float g_bufA[NSL * NPIX];
__device__ float g_bufB[NSL * NPIX];
__device__ float g_skel[NSL * NPIX];
__device__ float g_acc[8];

__global__ void zero_acc_kernel() {
    if (threadIdx.x < 8) g_acc[threadIdx.x] = 0.0f;
}

__global__ void init_kernel(const float4* __restrict__ pred,
                            const int4* __restrict__ tgt) {
    float a4 = 0.f, a5 = 0.f, a6 = 0.f;
    const int n4 = HALF / 4;
    float4* img4 = (float4*)g_img0;
    const int stride = gridDim.x * blockDim.x;
    for (int i = blockIdx.x * blockDim.x + threadIdx.x; i < n4; i += stride) {
        float4 x = pred[i];
        int4 ti = tgt[i];
        float4 p, t;
        p.x = 1.0f / (1.0f + __expf(-x.x));
        p.y = 1.0f / (1.0f + __expf(-x.y));
        p.z = 1.0f / (1.0f + __expf(-x.z));
        p.w = 1.0f / (1.0f + __expf(-x.w));
        t.x = (float)ti.x; t.y = (float)ti.y; t.z = (float)ti.z; t.w = (float)ti.w;
        img4[i] = p;
        img4[n4 + i] = t;
        a4 += p.x * t.x + p.y * t.y + p.z * t.z + p.w * t.w;
        a5 += p.x + p.y + p.z + p.w;
        a6 += t.x + t.y + t.z + t.w;
    }
    #pragma unroll
    for (int o = 16; o; o >>= 1) {
        a4 += __shfl_down_sync(0xffffffffu, a4, o);
        a5 += __shfl_down_sync(0xffffffffu, a5, o);
        a6 += __shfl_down_sync(0xffffffffu, a6, o);
    }
    __shared__ float sr[3][8];
    int w = threadIdx.x >> 5, l = threadIdx.x & 31;
    if (l == 0) { sr[0][w] = a4; sr[1][w] = a5; sr[2][w] = a6; }
    __syncthreads();
    if (threadIdx.x == 0) {
        float s4 = 0.f, s5 = 0.f, s6 = 0.f;
        #pragma unroll
        for (int k = 0; k < 8; k++) { s4 += sr[0][k]; s5 += sr[1][k]; s6 += sr[2][k]; }
        atomicAdd(&g_acc[4], s4);
        atomicAdd(&g_acc[5], s5);
        atomicAdd(&g_acc[6], s6);
    }
}

// F fused skeleton steps; 512 threads; 3-buffer smem rotation => 1 barrier/step.
template<int F, bool FIRST, bool LAST>
__global__ __launch_bounds__(512, 3)
void fused_kernel(int src_sel, int dst_sel) {
    constexpr int R  = F + 1;
    constexpr int H2 = TYO + 2 * R;
    constexpr int BUF = H2 * W2;

    __shared__ float sX[BUF];
    __shared__ float sY[BUF];
    __shared__ float sZ[BUF];
    __shared__ float sred[32];

    const float* in = (src_sel == 0) ? g_img0 : ((src_sel == 1) ? g_bufA : g_bufB);
    float* eout = (dst_sel == 1) ? g_bufA : g_bufB;

    const int bx = blockIdx.x * TXO;
    const int by = blockIdx.y * TYO;
    const int z  = blockIdx.z;
    const float* img = in + z * NPIX;
    const int tx = threadIdx.x;        // 0..31
    const int ty = threadIdx.y;        // 0..15
    const int tid = ty * 32 + tx;
    const bool border = (blockIdx.x == 0) | (blockIdx.x == gridDim.x - 1) |
                        (blockIdx.y == 0) | (blockIdx.y == gridDim.y - 1);

    // ---- load tile with halo (vector loads; OOB whole-vector) ----
    if (!border) {
        for (int i = tid; i < 36 * H2; i += 512) {
            int vy = i / 36, vx = i - vy * 36;
            *(float4*)&sX[vy * W2 + 4 * vx] =
                *(const float4*)&img[(by - R + vy) * W + (bx - PADX + 4 * vx)];
        }
    } else {
        for (int i = tid; i < 36 * H2; i += 512) {
            int vy = i / 36, vx = i - vy * 36;
            int gx0 = bx - PADX + 4 * vx;
            int gy  = by - R + vy;
            float4 v = make_float4(INFINITY, INFINITY, INFINITY, INFINITY);
            if ((unsigned)gx0 < W && (unsigned)gy < H)
                v = *(const float4*)&img[gy * W + gx0];
            *(float4*)&sX[vy * W2 + 4 * vx] = v;
        }
    }

    const int gi = z * NPIX + (by + ty) * W + (bx + 4 * tx);
    float4 sk;
    if (FIRST) sk = make_float4(0.f, 0.f, 0.f, 0.f);
    else       sk = *(const float4*)&g_skel[gi];
    __syncthreads();

    float* Sa = sX;   // e_st
    float* Sb = sY;   // erode target
    float* Sc = sZ;

    #pragma unroll
    for (int st = 0; st < F; st++) {
        // ---- erode; region shrinks with stage: rows [1+st, H2-1-st) ----
        const int nrows = H2 - 2 - 2 * st;
        const int ntask = nrows * 34;
        for (int i = tid; i < ntask; i += 512) {
            int ly = i / 34;
            int vx = i - ly * 34 + 1;
            ly += 1 + st;
            int o = ly * W2 + 4 * vx;
            float4 c = *(float4*)&Sa[o];
            float4 u = *(float4*)&Sa[o - W2];
            float4 d = *(float4*)&Sa[o + W2];
            float l = Sa[o - 1], r = Sa[o + 4];
            float4 e;
            e.x = fminf(fminf(c.x, fminf(u.x, d.x)), fminf(l,   c.y));
            e.y = fminf(fminf(c.y, fminf(u.y, d.y)), fminf(c.x, c.z));
            e.z = fminf(fminf(c.z, fminf(u.z, d.z)), fminf(c.y, c.w));
            e.w = fminf(fminf(c.w, fminf(u.w, d.w)), fminf(c.z, r));
            if (border) {
                int gx0 = bx - PADX + 4 * vx;
                int gy  = by - R + ly;
                if (!((unsigned)gx0 < W && (unsigned)gy < H)) {
                    e.x = INFINITY; e.y = INFINITY; e.z = INFINITY; e.w = INFINITY;
                }
            }
            *(float4*)&Sb[o] = e;
        }
        __syncthreads();

        // ---- dilate3x3(e_{st+1}) + delta + skel (no barrier after) ----
        {
            int o = (R + ty) * W2 + PADX + 4 * tx;
            float4 vu = *(float4*)&Sb[o - W2];
            float4 vm = *(float4*)&Sb[o];
            float4 vd = *(float4*)&Sb[o + W2];
            float lu = Sb[o - W2 - 1], ru = Sb[o - W2 + 4];
            float lm = Sb[o - 1],      rm = Sb[o + 4];
            float ld = Sb[o + W2 - 1], rd = Sb[o + W2 + 4];
            if (border) {
                const int gy = by + ty;
                const int gx0 = bx + 4 * tx;
                if (gy == 0) {
                    vu = make_float4(-INFINITY, -INFINITY, -INFINITY, -INFINITY);
                    lu = -INFINITY; ru = -INFINITY;
                }
                if (gy == H - 1) {
                    vd = make_float4(-INFINITY, -INFINITY, -INFINITY, -INFINITY);
                    ld = -INFINITY; rd = -INFINITY;
                }
                if (gx0 == 0)     { lu = -INFINITY; lm = -INFINITY; ld = -INFINITY; }
                if (gx0 == W - 4) { ru = -INFINITY; rm = -INFINITY; rd = -INFINITY; }
            }
            float4 hu, hm, hd, dd;
            hu.x = fmaxf(lu,   fmaxf(vu.x, vu.y));
            hu.y = fmaxf(vu.x, fmaxf(vu.y, vu.z));
            hu.z = fmaxf(vu.y, fmaxf(vu.z, vu.w));
            hu.w = fmaxf(vu.z, fmaxf(vu.w, ru));
            hm.x = fmaxf(lm,   fmaxf(vm.x, vm.y));
            hm.y = fmaxf(vm.x, fmaxf(vm.y, vm.z));
            hm.z = fmaxf(vm.y, fmaxf(vm.z, vm.w));
            hm.w = fmaxf(vm.z, fmaxf(vm.w, rm));
            hd.x = fmaxf(ld,   fmaxf(vd.x, vd.y));
            hd.y = fmaxf(vd.x, fmaxf(vd.y, vd.z));
            hd.z = fmaxf(vd.y, fmaxf(vd.z, vd.w));
            hd.w = fmaxf(vd.z, fmaxf(vd.w, rd));
            dd.x = fmaxf(hu.x, fmaxf(hm.x, hd.x));
            dd.y = fmaxf(hu.y, fmaxf(hm.y, hd.y));
            dd.z = fmaxf(hu.z, fmaxf(hm.z, hd.z));
            dd.w = fmaxf(hu.w, fmaxf(hm.w, hd.w));

            float4 ek = *(float4*)&Sa[o];
            float4 de;
            de.x = fmaxf(ek.x - dd.x, 0.f);
            de.y = fmaxf(ek.y - dd.y, 0.f);
            de.z = fmaxf(ek.z - dd.z, 0.f);
            de.w = fmaxf(ek.w - dd.w, 0.f);
            if (FIRST && st == 0) {
                sk = de;
            } else {
                sk.x += fmaxf(de.x - sk.x * de.x, 0.f);
                sk.y += fmaxf(de.y - sk.y * de.y, 0.f);
                sk.z += fmaxf(de.z - sk.z * de.z, 0.f);
                sk.w += fmaxf(de.w - sk.w * de.w, 0.f);
            }
            if (st == F - 1 && !LAST) {
                *(float4*)&eout[gi] = vm;       // e_{st+1} center vector
                *(float4*)&g_skel[gi] = sk;
            }
        }
        // rotate buffers: writes in next erode go to a buffer untouched by
        // the (possibly still in-flight) dilate reads of Sa/Sb -> no barrier.
        float* t0 = Sa; Sa = Sb; Sb = Sc; Sc = t0;
    }

    if (LAST) {
        float4 cp = (z < 8) ? *(const float4*)&g_img0[gi + HALF]
                            : *(const float4*)&g_img0[gi - HALF];
        float sprod = sk.x * cp.x + sk.y * cp.y + sk.z * cp.z + sk.w * cp.w;
        float ssum  = sk.x + sk.y + sk.z + sk.w;
        #pragma unroll
        for (int o = 16; o; o >>= 1) {
            sprod += __shfl_down_sync(0xffffffffu, sprod, o);
            ssum  += __shfl_down_sync(0xffffffffu, ssum,  o);
        }
        int w = tid >> 5, l = tid & 31;
        if (l == 0) { sred[w] = sprod; sred[16 + w] = ssum; }
        __syncthreads();
        if (tid < 32) {
            // 16 warps: lanes 0..15 hold sprod parts, 16..31 hold ssum parts
            float v = sred[tid];
            v += __shfl_down_sync(0xffffffffu, v, 8, 16);
            v += __shfl_down_sync(0xffffffffu, v, 4, 16);
            v += __shfl_down_sync(0xffffffffu, v, 2, 16);
            v += __shfl_down_sync(0xffffffffu, v, 1, 16);
            if (tid == 0) {
                if (z < 8) atomicAdd(&g_acc[0], v); else atomicAdd(&g_acc[2], v);
            }
            if (tid == 16) {
                if (z < 8) atomicAdd(&g_acc[1], v); else atomicAdd(&g_acc[3], v);
            }
        }
    }
}

__global__ void finalize_kernel(float* out) {
    const float SMOOTH = 1.0f;
    float tprec = (g_acc[0] + SMOOTH) / (g_acc[1] + SMOOTH);
    float tsens = (g_acc[2] + SMOOTH) / (g_acc[3] + SMOOTH);
    float cl_dice = 2.0f * tprec * tsens / (tprec + tsens + 1e-7f);
    float dice = (2.0f * g_acc[4] + SMOOTH) / (g_acc[5] + g_acc[6] + SMOOTH);
    float combined = 0.5f * dice + 0.5f * cl_dice;
    out[0] = 1.0f - combined;
}

extern "C" void kernel_launch(void* const* d_in, const int* in_sizes, int n_in,
                              void* d_out, int out_size) {
    const float4* pred = (const float4*)d_in[0];
    const int4* target = (const int4*)d_in[1];

    zero_acc_kernel<<<1, 32>>>();
    init_kernel<<<2048, 256>>>(pred, target);

    dim3 blk(32, 16);
    dim3 grd(W / TXO, H / TYO, NSL);
    fused_kernel<4, true,  false><<<grd, blk>>>(0, 1);   // steps 0-3
    fused_kernel<4, false, false><<<grd, blk>>>(1, 2);   // steps 4-7
    fused_kernel<3, false, true ><<<grd, blk>>>(2, 1);   // steps 8-10 + reductions

    finalize_kernel<<<1, 1>>>((float*)d_out);
}

// round 8
// speedup vs baseline: 5.5645x; 1.2469x over previous
#include <cuda_runtime.h>
#include <math.h>

#define H 1024
#define W 1024
#define NPIX (H * W)
#define NSL 16
#define HALF (8 * NPIX)

#define TXO 128
#define TYO 32
#define PADX 8
#define W2 144          // padded smem row; center pixels at lx = 8..135

__device__ float g_img0[NSL * NPIX];
__device__ float g_bufA[NSL * NPIX];
__device__ float g_bufB[NSL * NPIX];
__device__ float g_skel[NSL * NPIX];
__device__ float g_acc[8];

__global__ void zero_acc_kernel() {
    if (threadIdx.x < 8) g_acc[threadIdx.x] = 0.0f;
}

__global__ void init_kernel(const float4* __restrict__ pred,
                            const int4* __restrict__ tgt) {
    float a4 = 0.f, a5 = 0.f, a6 = 0.f;
    const int n4 = HALF / 4;
    float4* img4 = (float4*)g_img0;
    const int stride = gridDim.x * blockDim.x;
    for (int i = blockIdx.x * blockDim.x + threadIdx.x; i < n4; i += stride) {
        float4 x = pred[i];
        int4 ti = tgt[i];
        float4 p, t;
        p.x = 1.0f / (1.0f + __expf(-x.x));
        p.y = 1.0f / (1.0f + __expf(-x.y));
        p.z = 1.0f / (1.0f + __expf(-x.z));
        p.w = 1.0f / (1.0f + __expf(-x.w));
        t.x = (float)ti.x; t.y = (float)ti.y; t.z = (float)ti.z; t.w = (float)ti.w;
        img4[i] = p;
        img4[n4 + i] = t;
        a4 += p.x * t.x + p.y * t.y + p.z * t.z + p.w * t.w;
        a5 += p.x + p.y + p.z + p.w;
        a6 += t.x + t.y + t.z + t.w;
    }
    #pragma unroll
    for (int o = 16; o; o >>= 1) {
        a4 += __shfl_down_sync(0xffffffffu, a4, o);
        a5 += __shfl_down_sync(0xffffffffu, a5, o);
        a6 += __shfl_down_sync(0xffffffffu, a6, o);
    }
    __shared__ float sr[3][8];
    int w = threadIdx.x >> 5, l = threadIdx.x & 31;
    if (l == 0) { sr[0][w] = a4; sr[1][w] = a5; sr[2][w] = a6; }
    __syncthreads();
    if (threadIdx.x == 0) {
        float s4 = 0.f, s5 = 0.f, s6 = 0.f;
        #pragma unroll
        for (int k = 0; k < 8; k++) { s4 += sr[0][k]; s5 += sr[1][k]; s6 += sr[2][k]; }
        atomicAdd(&g_acc[4], s4);
        atomicAdd(&g_acc[5], s5);
        atomicAdd(&g_acc[6], s6);
    }
}

// F fused steps; 512 threads; each thread owns 2 rows of a 128x32 tile.
// 3-buffer rotation => 1 barrier per step. Dynamic smem (3 buffers).
template<int F, bool FIRST, bool LAST>
__global__ __launch_bounds__(512, 3)
void fused_kernel(int src_sel, int dst_sel) {
    constexpr int R  = F + 1;
    constexpr int H2 = TYO + 2 * R;
    constexpr int BUF = H2 * W2;

    extern __shared__ float smem[];
    float* sX = smem;
    float* sY = smem + BUF;
    float* sZ = smem + 2 * BUF;
    __shared__ float sred[32];

    const float* in = (src_sel == 0) ? g_img0 : ((src_sel == 1) ? g_bufA : g_bufB);
    float* eout = (dst_sel == 1) ? g_bufA : g_bufB;

    const int bx = blockIdx.x * TXO;
    const int by = blockIdx.y * TYO;
    const int z  = blockIdx.z;
    const float* img = in + z * NPIX;
    const int tx = threadIdx.x;        // 0..31 (x vector)
    const int ty = threadIdx.y;        // 0..15 (row pair)
    const int tid = ty * 32 + tx;
    const bool border = (blockIdx.x == 0) | (blockIdx.x == gridDim.x - 1) |
                        (blockIdx.y == 0) | (blockIdx.y == gridDim.y - 1);

    // ---- load tile with halo ----
    if (!border) {
        for (int i = tid; i < 36 * H2; i += 512) {
            int vy = i / 36, vx = i - vy * 36;
            *(float4*)&sX[vy * W2 + 4 * vx] =
                *(const float4*)&img[(by - R + vy) * W + (bx - PADX + 4 * vx)];
        }
    } else {
        for (int i = tid; i < 36 * H2; i += 512) {
            int vy = i / 36, vx = i - vy * 36;
            int gx0 = bx - PADX + 4 * vx;
            int gy  = by - R + vy;
            float4 v = make_float4(INFINITY, INFINITY, INFINITY, INFINITY);
            if ((unsigned)gx0 < W && (unsigned)gy < H)
                v = *(const float4*)&img[gy * W + gx0];
            *(float4*)&sX[vy * W2 + 4 * vx] = v;
        }
    }

    const int py0 = 2 * ty;
    const int gi0 = z * NPIX + (by + py0) * W + (bx + 4 * tx);
    const int gi1 = gi0 + W;
    float4 sk0, sk1;
    if (FIRST) {
        sk0 = make_float4(0.f, 0.f, 0.f, 0.f);
        sk1 = sk0;
    } else {
        sk0 = *(const float4*)&g_skel[gi0];
        sk1 = *(const float4*)&g_skel[gi1];
    }
    __syncthreads();

    float* Sa = sX;
    float* Sb = sY;
    float* Sc = sZ;

    #pragma unroll
    for (int st = 0; st < F; st++) {
        // ---- erode; rows [1+st, H2-1-st), processed in pairs ----
        const int npairs = (H2 - 2 - 2 * st) >> 1;
        const int ntask = npairs * 34;
        for (int i = tid; i < ntask; i += 512) {
            int pj = i / 34;
            int vx = i - pj * 34 + 1;
            int y0 = 1 + st + 2 * pj;
            int o1 = y0 * W2 + 4 * vx;
            int o2 = o1 + W2;
            float4 c0 = *(float4*)&Sa[o1 - W2];
            float4 c1 = *(float4*)&Sa[o1];
            float4 c2 = *(float4*)&Sa[o2];
            float4 c3 = *(float4*)&Sa[o2 + W2];
            float l1 = Sa[o1 - 1], r1 = Sa[o1 + 4];
            float l2 = Sa[o2 - 1], r2 = Sa[o2 + 4];
            float4 e1, e2;
            e1.x = fminf(fminf(c1.x, fminf(c0.x, c2.x)), fminf(l1,   c1.y));
            e1.y = fminf(fminf(c1.y, fminf(c0.y, c2.y)), fminf(c1.x, c1.z));
            e1.z = fminf(fminf(c1.z, fminf(c0.z, c2.z)), fminf(c1.y, c1.w));
            e1.w = fminf(fminf(c1.w, fminf(c0.w, c2.w)), fminf(c1.z, r1));
            e2.x = fminf(fminf(c2.x, fminf(c1.x, c3.x)), fminf(l2,   c2.y));
            e2.y = fminf(fminf(c2.y, fminf(c1.y, c3.y)), fminf(c2.x, c2.z));
            e2.z = fminf(fminf(c2.z, fminf(c1.z, c3.z)), fminf(c2.y, c2.w));
            e2.w = fminf(fminf(c2.w, fminf(c1.w, c3.w)), fminf(c2.z, r2));
            if (border) {
                int gx0 = bx - PADX + 4 * vx;
                int gy  = by - R + y0;
                bool okx = (unsigned)gx0 < W;
                if (!(okx && (unsigned)gy < H))
                    e1 = make_float4(INFINITY, INFINITY, INFINITY, INFINITY);
                if (!(okx && (unsigned)(gy + 1) < H))
                    e2 = make_float4(INFINITY, INFINITY, INFINITY, INFINITY);
            }
            *(float4*)&Sb[o1] = e1;
            *(float4*)&Sb[o2] = e2;
        }
        __syncthreads();

        // ---- dilate3x3(e') + delta + skel for this thread's 2 rows ----
        {
            int o = (R + py0) * W2 + PADX + 4 * tx;
            float4 ra = *(float4*)&Sb[o - W2];      // row py0-1
            float4 rb = *(float4*)&Sb[o];           // row py0
            float4 rc = *(float4*)&Sb[o + W2];      // row py1
            float4 rd = *(float4*)&Sb[o + 2 * W2];  // row py1+1
            float la = Sb[o - W2 - 1],     rra = Sb[o - W2 + 4];
            float lb = Sb[o - 1],          rrb = Sb[o + 4];
            float lc = Sb[o + W2 - 1],     rrc = Sb[o + W2 + 4];
            float ld = Sb[o + 2 * W2 - 1], rrd = Sb[o + 2 * W2 + 4];
            if (border) {
                const int gy0 = by + py0;
                const int gx0 = bx + 4 * tx;
                if (gy0 == 0) {
                    ra = make_float4(-INFINITY, -INFINITY, -INFINITY, -INFINITY);
                    la = -INFINITY; rra = -INFINITY;
                }
                if (gy0 + 1 == H - 1) {
                    rd = make_float4(-INFINITY, -INFINITY, -INFINITY, -INFINITY);
                    ld = -INFINITY; rrd = -INFINITY;
                }
                if (gx0 == 0)     { la = -INFINITY; lb = -INFINITY; lc = -INFINITY; ld = -INFINITY; }
                if (gx0 == W - 4) { rra = -INFINITY; rrb = -INFINITY; rrc = -INFINITY; rrd = -INFINITY; }
            }
            float4 ha, hb, hc, hd;
            ha.x = fmaxf(la,   fmaxf(ra.x, ra.y));
            ha.y = fmaxf(ra.x, fmaxf(ra.y, ra.z));
            ha.z = fmaxf(ra.y, fmaxf(ra.z, ra.w));
            ha.w = fmaxf(ra.z, fmaxf(ra.w, rra));
            hb.x = fmaxf(lb,   fmaxf(rb.x, rb.y));
            hb.y = fmaxf(rb.x, fmaxf(rb.y, rb.z));
            hb.z = fmaxf(rb.y, fmaxf(rb.z, rb.w));
            hb.w = fmaxf(rb.z, fmaxf(rb.w, rrb));
            hc.x = fmaxf(lc,   fmaxf(rc.x, rc.y));
            hc.y = fmaxf(rc.x, fmaxf(rc.y, rc.z));
            hc.z = fmaxf(rc.y, fmaxf(rc.z, rc.w));
            hc.w = fmaxf(rc.z, fmaxf(rc.w, rrc));
            hd.x = fmaxf(ld,   fmaxf(rd.x, rd.y));
            hd.y = fmaxf(rd.x, fmaxf(rd.y, rd.z));
            hd.z = fmaxf(rd.y, fmaxf(rd.z, rd.w));
            hd.w = fmaxf(rd.z, fmaxf(rd.w, rrd));

            float4 d0, d1;
            d0.x = fmaxf(ha.x, fmaxf(hb.x, hc.x));
            d0.y = fmaxf(ha.y, fmaxf(hb.y, hc.y));
            d0.z = fmaxf(ha.z, fmaxf(hb.z, hc.z));
            d0.w = fmaxf(ha.w, fmaxf(hb.w, hc.w));
            d1.x = fmaxf(hb.x, fmaxf(hc.x, hd.x));
            d1.y = fmaxf(hb.y, fmaxf(hc.y, hd.y));
            d1.z = fmaxf(hb.z, fmaxf(hc.z, hd.z));
            d1.w = fmaxf(hb.w, fmaxf(hc.w, hd.w));

            float4 ek0 = *(float4*)&Sa[o];
            float4 ek1 = *(float4*)&Sa[o + W2];
            float4 de0, de1;
            de0.x = fmaxf(ek0.x - d0.x, 0.f);
            de0.y = fmaxf(ek0.y - d0.y, 0.f);
            de0.z = fmaxf(ek0.z - d0.z, 0.f);
            de0.w = fmaxf(ek0.w - d0.w, 0.f);
            de1.x = fmaxf(ek1.x - d1.x, 0.f);
            de1.y = fmaxf(ek1.y - d1.y, 0.f);
            de1.z = fmaxf(ek1.z - d1.z, 0.f);
            de1.w = fmaxf(ek1.w - d1.w, 0.f);
            if (FIRST && st == 0) {
                sk0 = de0; sk1 = de1;
            } else {
                sk0.x += fmaxf(de0.x - sk0.x * de0.x, 0.f);
                sk0.y += fmaxf(de0.y - sk0.y * de0.y, 0.f);
                sk0.z += fmaxf(de0.z - sk0.z * de0.z, 0.f);
                sk0.w += fmaxf(de0.w - sk0.w * de0.w, 0.f);
                sk1.x += fmaxf(de1.x - sk1.x * de1.x, 0.f);
                sk1.y += fmaxf(de1.y - sk1.y * de1.y, 0.f);
                sk1.z += fmaxf(de1.z - sk1.z * de1.z, 0.f);
                sk1.w += fmaxf(de1.w - sk1.w * de1.w, 0.f);
            }
            if (st == F - 1 && !LAST) {
                *(float4*)&eout[gi0] = rb;
                *(float4*)&eout[gi1] = rc;
                *(float4*)&g_skel[gi0] = sk0;
                *(float4*)&g_skel[gi1] = sk1;
            }
        }
        // rotate buffers (safe: next erode writes only old Sc, untouched by
        // this step's dilate reads of Sa/Sb)
        float* t0 = Sa; Sa = Sb; Sb = Sc; Sc = t0;
    }

    if (LAST) {
        float4 cp0 = (z < 8) ? *(const float4*)&g_img0[gi0 + HALF]
                             : *(const float4*)&g_img0[gi0 - HALF];
        float4 cp1 = (z < 8) ? *(const float4*)&g_img0[gi1 + HALF]
                             : *(const float4*)&g_img0[gi1 - HALF];
        float sprod = sk0.x * cp0.x + sk0.y * cp0.y + sk0.z * cp0.z + sk0.w * cp0.w
                    + sk1.x * cp1.x + sk1.y * cp1.y + sk1.z * cp1.z + sk1.w * cp1.w;
        float ssum  = sk0.x + sk0.y + sk0.z + sk0.w
                    + sk1.x + sk1.y + sk1.z + sk1.w;
        #pragma unroll
        for (int o = 16; o; o >>= 1) {
            sprod += __shfl_down_sync(0xffffffffu, sprod, o);
            ssum  += __shfl_down_sync(0xffffffffu, ssum,  o);
        }
        int w = tid >> 5, l = tid & 31;
        if (l == 0) { sred[w] = sprod; sred[16 + w] = ssum; }
        __syncthreads();
        if (tid < 32) {
            float v = sred[tid];
            v += __shfl_down_sync(0xffffffffu, v, 8, 16);
            v += __shfl_down_sync(0xffffffffu, v, 4, 16);
            v += __shfl_down_sync(0xffffffffu, v, 2, 16);
            v += __shfl_down_sync(0xffffffffu, v, 1, 16);
            if (tid == 0) {
                if (z < 8) atomicAdd(&g_acc[0], v); else atomicAdd(&g_acc[2], v);
            }
            if (tid == 16) {
                if (z < 8) atomicAdd(&g_acc[1], v); else atomicAdd(&g_acc[3], v);
            }
        }
    }
}

__global__ void finalize_kernel(float* out) {
    const float SMOOTH = 1.0f;
    float tprec = (g_acc[0] + SMOOTH) / (g_acc[1] + SMOOTH);
    float tsens = (g_acc[2] + SMOOTH) / (g_acc[3] + SMOOTH);
    float cl_dice = 2.0f * tprec * tsens / (tprec + tsens + 1e-7f);
    float dice = (2.0f * g_acc[4] + SMOOTH) / (g_acc[5] + g_acc[6] + SMOOTH);
    float combined = 0.5f * dice + 0.5f * cl_dice;
    out[0] = 1.0f - combined;
}

extern "C" void kernel_launch(void* const* d_in, const int* in_sizes, int n_in,
                              void* d_out, int out_size) {
    const float4* pred = (const float4*)d_in[0];
    const int4* target = (const int4*)d_in[1];

    constexpr int SMEM_F4 = 3 * (TYO + 10) * W2 * 4;   // 72576 B
    constexpr int SMEM_F3 = 3 * (TYO + 8)  * W2 * 4;   // 69120 B
    static bool attr_done = false;
    if (!attr_done) {
        cudaFuncSetAttribute(fused_kernel<4, true,  false>,
                             cudaFuncAttributeMaxDynamicSharedMemorySize, SMEM_F4);
        cudaFuncSetAttribute(fused_kernel<4, false, false>,
                             cudaFuncAttributeMaxDynamicSharedMemorySize, SMEM_F4);
        cudaFuncSetAttribute(fused_kernel<3, false, true>,
                             cudaFuncAttributeMaxDynamicSharedMemorySize, SMEM_F3);
        attr_done = true;
    }

    zero_acc_kernel<<<1, 32>>>();
    init_kernel<<<2048, 256>>>(pred, target);

    dim3 blk(32, 16);
    dim3 grd(W / TXO, H / TYO, NSL);
    fused_kernel<4, true,  false><<<grd, blk, SMEM_F4>>>(0, 1);  // steps 0-3
    fused_kernel<4, false, false><<<grd, blk, SMEM_F4>>>(1, 2);  // steps 4-7
    fused_kernel<3, false, true ><<<grd, blk, SMEM_F3>>>(2, 1);  // steps 8-10

    finalize_kernel<<<1, 1>>>((float*)d_out);
}